// round 2
// baseline (speedup 1.0000x reference)
#include <cuda_runtime.h>
#include <cuda_bf16.h>
#include <cstdint>

// Problem constants (from reference): B=32, N=8192, C=512, K=128
#define PB 32
#define PN 8192
#define PC 512
#define PK 128

// -----------------------------------------------------------------------------
// Kernel A: gather col[b,n] = one_hot[b, n, id] and write to out[0 : B*N].
// One thread per (b,n) element. Strided gather (stride = C floats = 2 KB),
// spread across the whole chip so the L1tex wavefront work parallelizes.
// -----------------------------------------------------------------------------
__global__ void gather_col_kernel(const float* __restrict__ one_hot,
                                  const int* __restrict__ id_ptr,
                                  float* __restrict__ out)
{
    const int id = __ldg(id_ptr);
    int idx = blockIdx.x * blockDim.x + threadIdx.x;  // 0 .. B*N-1
    if (idx < PB * PN) {
        float v = __ldg(one_hot + (size_t)idx * PC + id);
        out[idx] = v;
    }
}

// -----------------------------------------------------------------------------
// Kernel B: per-batch stable compaction of indices where col != 0.
// One CTA per batch, 1024 threads, 8 contiguous elements per thread.
// col is read back from out[0:B*N] (L2-hot, written by kernel A).
// indices written as float to out[B*N + b*K + j].
// -----------------------------------------------------------------------------
__global__ void compact_idx_kernel(const float* __restrict__ col,
                                   float* __restrict__ out_idx)
{
    const int b = blockIdx.x;
    const int t = threadIdx.x;          // 0..1023
    const int lane = t & 31;
    const int wid = t >> 5;             // 0..31

    const float* cb = col + (size_t)b * PN;

    // Vectorized load: 8 contiguous floats per thread (two float4)
    float4 a0 = reinterpret_cast<const float4*>(cb)[t * 2 + 0];
    float4 a1 = reinterpret_cast<const float4*>(cb)[t * 2 + 1];
    float v[8] = {a0.x, a0.y, a0.z, a0.w, a1.x, a1.y, a1.z, a1.w};

    int cnt = 0;
#pragma unroll
    for (int i = 0; i < 8; i++) cnt += (v[i] != 0.0f);

    // Warp-level inclusive scan of per-thread counts
    int inc = cnt;
#pragma unroll
    for (int d = 1; d < 32; d <<= 1) {
        int y = __shfl_up_sync(0xffffffffu, inc, d);
        if (lane >= d) inc += y;
    }

    __shared__ int wtot[32];
    if (lane == 31) wtot[wid] = inc;
    __syncthreads();

    // Warp 0 scans the 32 warp totals into exclusive offsets
    if (wid == 0) {
        int wv = wtot[lane];
        int winc = wv;
#pragma unroll
        for (int d = 1; d < 32; d <<= 1) {
            int y = __shfl_up_sync(0xffffffffu, winc, d);
            if (lane >= d) winc += y;
        }
        wtot[lane] = winc - wv;   // exclusive prefix for this warp
    }
    __syncthreads();

    int excl = wtot[wid] + (inc - cnt);   // exclusive offset for this thread

    float* ob = out_idx + (size_t)b * PK;
    const int n0 = t * 8;
    int pos = excl;
#pragma unroll
    for (int i = 0; i < 8; i++) {
        if (v[i] != 0.0f) {
            if (pos < PK) ob[pos] = (float)(n0 + i);
            pos++;
        }
    }
}

extern "C" void kernel_launch(void* const* d_in, const int* in_sizes, int n_in,
                              void* d_out, int out_size)
{
    const float* one_hot = (const float*)d_in[0];
    const int*   id_ptr  = (const int*)d_in[1];
    float*       out     = (float*)d_out;

    (void)in_sizes; (void)n_in; (void)out_size;

    // Kernel A: full-chip gather of the id column
    {
        const int total = PB * PN;             // 262144
        const int tpb = 256;
        const int nb = (total + tpb - 1) / tpb; // 1024 blocks
        gather_col_kernel<<<nb, tpb>>>(one_hot, id_ptr, out);
    }

    // Kernel B: per-batch ordered compaction (reads col from L2)
    {
        compact_idx_kernel<<<PB, 1024>>>(out, out + (size_t)PB * PN);
    }
}

// round 3
// speedup vs baseline: 1.0775x; 1.0775x over previous
#include <cuda_runtime.h>
#include <cuda_bf16.h>
#include <cstdint>

// Problem constants: B=32, N=8192, C=512, K=128
#define PB   32
#define PN   8192
#define PC   512
#define PK   128
#define SEGS 32       // CTAs per batch
#define TPB  256      // threads per CTA = elements per CTA  (SEGS*TPB = PN)

// Scratch for cross-CTA aggregate exchange. Zero-initialized at module load;
// the kernel restores it to all-zeros at the end of every launch, so each
// graph replay sees identical starting state (deterministic, allocation-free).
__device__ unsigned int g_counts[PB * SEGS];
__device__ unsigned int g_done[PB];

__global__ void fused_filter_kernel(const float* __restrict__ one_hot,
                                    const int* __restrict__ id_ptr,
                                    float* __restrict__ out)
{
    const int g    = blockIdx.x;        // 0 .. PB*SEGS-1
    const int b    = g >> 5;            // batch
    const int seg  = g & (SEGS - 1);    // segment within batch
    const int t    = threadIdx.x;       // 0..255
    const int lane = t & 31;
    const int wid  = t >> 5;            // 0..7

    const int id = __ldg(id_ptr);
    const int n  = seg * TPB + t;                 // position within batch
    const size_t idx = (size_t)b * PN + n;

    // --- gather the id column and emit block_id output ---
    float v = __ldg(one_hot + idx * PC + id);
    out[idx] = v;

    // --- intra-CTA ordered rank of nonzeros ---
    const bool flag = (v != 0.0f);
    unsigned ballot = __ballot_sync(0xffffffffu, flag);
    int warp_cnt     = __popc(ballot);
    int rank_in_warp = __popc(ballot & ((1u << lane) - 1u));

    __shared__ int s_wcnt[8];
    __shared__ int s_base;
    if (lane == 0) s_wcnt[wid] = warp_cnt;
    __syncthreads();

    int warp_prefix = 0;
    int cta_cnt = 0;
#pragma unroll
    for (int w = 0; w < 8; w++) {
        int c = s_wcnt[w];
        if (w < wid) warp_prefix += c;
        cta_cnt += c;
    }

    // --- publish this CTA's aggregate (count+1 so 0 == "not ready") ---
    if (t == 0) atomicExch(&g_counts[g], (unsigned)(cta_cnt + 1));

    // --- depth-1 lookback: warp 0 polls all predecessor aggregates in parallel ---
    if (wid == 0) {
        unsigned c = 0;
        if (lane < seg) {
            unsigned int* slot = &g_counts[b * SEGS + lane];
            do { c = atomicAdd(slot, 0u); } while (c == 0u);
            c -= 1u;
        }
        __syncwarp();
#pragma unroll
        for (int d = 16; d > 0; d >>= 1)
            c += __shfl_down_sync(0xffffffffu, c, d);
        if (lane == 0) s_base = (int)c;
    }
    __syncthreads();

    // --- ordered scatter of indices (as float, per output dtype) ---
    if (flag) {
        int pos = s_base + warp_prefix + rank_in_warp;
        if (pos < PK)
            out[(size_t)PB * PN + (size_t)b * PK + pos] = (float)n;
    }

    // --- self-cleaning scratch: last CTA of each batch zeroes its slots.
    //     'done' is only incremented after the poll completed, so when the
    //     32nd increment lands, no CTA of this batch will read counts again.
    if (t == 0) {
        unsigned d = atomicAdd(&g_done[b], 1u);
        if (d == SEGS - 1) {
            __threadfence();
#pragma unroll
            for (int i = 0; i < SEGS; i++)
                atomicExch(&g_counts[b * SEGS + i], 0u);
            atomicExch(&g_done[b], 0u);
        }
    }
}

extern "C" void kernel_launch(void* const* d_in, const int* in_sizes, int n_in,
                              void* d_out, int out_size)
{
    const float* one_hot = (const float*)d_in[0];
    const int*   id_ptr  = (const int*)d_in[1];
    float*       out     = (float*)d_out;

    (void)in_sizes; (void)n_in; (void)out_size;

    fused_filter_kernel<<<PB * SEGS, TPB>>>(one_hot, id_ptr, out);
}